// round 2
// baseline (speedup 1.0000x reference)
#include <cuda_runtime.h>
#include <cuda_bf16.h>
#include <math.h>

// ---------------------------------------------------------------------------
// Problem constants
// ---------------------------------------------------------------------------
#define BB 4
#define SS 2048
#define HH 1024
#define NHEADS 8
#define HD 128
#define ROWS (BB*SS)          // 8192
#define METAD 256

// ---------------------------------------------------------------------------
// Scratch (device globals -- no allocation allowed)
// ---------------------------------------------------------------------------
__device__ float g_x   [(size_t)ROWS * HH];            // 32 MB  x = hidden + pos
__device__ float g_qkv [(size_t)ROWS * 3 * HH];        // 96 MB
__device__ float g_scr [(size_t)BB * NHEADS * SS * SS];// 512 MB attention scores
__device__ float g_ctx [(size_t)ROWS * HH];            // 32 MB
__device__ float g_att [(size_t)ROWS * HH];            // 32 MB
__device__ float g_h1  [(size_t)ROWS * METAD];         // 8 MB
__device__ float g_h2  [(size_t)ROWS * (METAD/2)];     // 4 MB

// ---------------------------------------------------------------------------
// Generic tiled SGEMM:  C = alpha * A * op(B) (+ bias) (+ C)
//   A : [M,K] row-major, leading dim lda
//   BT=true : B is [N,K] (row-major), C[m,n] = sum_k A[m,k]*B[n,k]
//   BT=false: B is [K,N] (row-major), C[m,n] = sum_k A[m,k]*B[k,n]
//   Batched via blockIdx.z = zo*innerCount + zi with independent offsets.
//   All of M,N multiples of 128; K multiple of 16 (true for every call here).
// ---------------------------------------------------------------------------
template<bool BT>
__global__ __launch_bounds__(256)
void sgemm_kernel(const float* __restrict__ A,
                  const float* __restrict__ B,
                  float* __restrict__ C,
                  int M, int N, int K,
                  int lda, int ldb, int ldc,
                  long long aOuter, long long aInner,
                  long long bOuter, long long bInner,
                  long long cOuter, long long cInner,
                  int innerCount,
                  const float* __restrict__ bias,
                  float alpha, int accumulate)
{
    const int z  = blockIdx.z;
    const int zo = z / innerCount;
    const int zi = z - zo * innerCount;
    A += zo * aOuter + zi * aInner;
    B += zo * bOuter + zi * bInner;
    C += zo * cOuter + zi * cInner;

    __shared__ float As[16][128];
    __shared__ float Bs[16][128];

    const int t    = threadIdx.x;
    const int tx   = t & 15;
    const int ty   = t >> 4;
    const int brow = blockIdx.y * 128;
    const int bcol = blockIdx.x * 128;

    float acc[8][8];
#pragma unroll
    for (int i = 0; i < 8; i++)
#pragma unroll
        for (int j = 0; j < 8; j++) acc[i][j] = 0.0f;

    for (int kt = 0; kt < K; kt += 16) {
        // ---- load A tile (128 x 16) transposed into As[k][m] ----
#pragma unroll
        for (int i = 0; i < 2; i++) {
            int idx = t + i * 256;            // 0..511
            int row = idx >> 2;               // 0..127
            int kv  = idx & 3;                // float4 within the 16-wide k slab
            float4 v = *reinterpret_cast<const float4*>(
                A + (long long)(brow + row) * lda + kt + kv * 4);
            As[kv * 4 + 0][row] = v.x;
            As[kv * 4 + 1][row] = v.y;
            As[kv * 4 + 2][row] = v.z;
            As[kv * 4 + 3][row] = v.w;
        }
        // ---- load B tile ----
        if (BT) {
#pragma unroll
            for (int i = 0; i < 2; i++) {
                int idx = t + i * 256;
                int row = idx >> 2;           // n within tile
                int kv  = idx & 3;
                float4 v = *reinterpret_cast<const float4*>(
                    B + (long long)(bcol + row) * ldb + kt + kv * 4);
                Bs[kv * 4 + 0][row] = v.x;
                Bs[kv * 4 + 1][row] = v.y;
                Bs[kv * 4 + 2][row] = v.z;
                Bs[kv * 4 + 3][row] = v.w;
            }
        } else {
#pragma unroll
            for (int i = 0; i < 2; i++) {
                int idx = t + i * 256;
                int row = idx >> 5;           // k row 0..15
                int c4  = idx & 31;           // float4 along n
                float4 v = *reinterpret_cast<const float4*>(
                    B + (long long)(kt + row) * ldb + bcol + c4 * 4);
                *reinterpret_cast<float4*>(&Bs[row][c4 * 4]) = v;
            }
        }
        __syncthreads();

#pragma unroll
        for (int k = 0; k < 16; k++) {
            float4 a0 = *reinterpret_cast<const float4*>(&As[k][ty * 8]);
            float4 a1 = *reinterpret_cast<const float4*>(&As[k][ty * 8 + 4]);
            float4 b0 = *reinterpret_cast<const float4*>(&Bs[k][tx * 8]);
            float4 b1 = *reinterpret_cast<const float4*>(&Bs[k][tx * 8 + 4]);
            float a[8] = {a0.x, a0.y, a0.z, a0.w, a1.x, a1.y, a1.z, a1.w};
            float b[8] = {b0.x, b0.y, b0.z, b0.w, b1.x, b1.y, b1.z, b1.w};
#pragma unroll
            for (int i = 0; i < 8; i++)
#pragma unroll
                for (int j = 0; j < 8; j++)
                    acc[i][j] = fmaf(a[i], b[j], acc[i][j]);
        }
        __syncthreads();
    }

    // ---- epilogue ----
#pragma unroll
    for (int i = 0; i < 8; i++) {
        long long crow = brow + ty * 8 + i;
        float* cp = C + crow * (long long)ldc + bcol + tx * 8;
#pragma unroll
        for (int j = 0; j < 8; j += 4) {
            float4 v;
            v.x = acc[i][j + 0] * alpha;
            v.y = acc[i][j + 1] * alpha;
            v.z = acc[i][j + 2] * alpha;
            v.w = acc[i][j + 3] * alpha;
            if (bias) {
                const float4 bv = *reinterpret_cast<const float4*>(
                    bias + bcol + tx * 8 + j);
                v.x += bv.x; v.y += bv.y; v.z += bv.z; v.w += bv.w;
            }
            if (accumulate) {
                const float4 ov = *reinterpret_cast<const float4*>(cp + j);
                v.x += ov.x; v.y += ov.y; v.z += ov.z; v.w += ov.w;
            }
            *reinterpret_cast<float4*>(cp + j) = v;
        }
    }
}

// ---------------------------------------------------------------------------
// x = hidden + pos (broadcast over batch), float4
// ---------------------------------------------------------------------------
__global__ void add_pos_kernel(const float* __restrict__ h,
                               const float* __restrict__ p,
                               float* __restrict__ x)
{
    long long i = (long long)blockIdx.x * blockDim.x + threadIdx.x; // float4 idx
    const long long P4 = (long long)SS * HH / 4;
    float4 hv = reinterpret_cast<const float4*>(h)[i];
    float4 pv = reinterpret_cast<const float4*>(p)[i % P4];
    hv.x += pv.x; hv.y += pv.y; hv.z += pv.z; hv.w += pv.w;
    reinterpret_cast<float4*>(x)[i] = hv;
}

// ---------------------------------------------------------------------------
// Row softmax over 2048 with key-mask (-1e9 where mask==0).
// mask is int32 (bool serialized as int32 by the harness).
// blockIdx.x = global row in [0, B*NHEADS*SS)
// ---------------------------------------------------------------------------
__global__ __launch_bounds__(256)
void softmax_kernel(float* __restrict__ S, const int* __restrict__ mask)
{
    const long long row = blockIdx.x;
    const int b = (int)(row >> 14);            // row / (NHEADS*SS)
    float* p = S + row * (long long)SS;
    const int* mrow = mask + (long long)b * SS;
    const int t = threadIdx.x;

    float vals[8];
    float m = -1e30f;
#pragma unroll
    for (int k = 0; k < 8; k++) {
        int j = t + k * 256;
        float v = p[j];
        v = (mrow[j] != 0) ? v : -1e9f;
        vals[k] = v;
        m = fmaxf(m, v);
    }
    __shared__ float red[256];
    red[t] = m; __syncthreads();
    for (int s = 128; s > 0; s >>= 1) {
        if (t < s) red[t] = fmaxf(red[t], red[t + s]);
        __syncthreads();
    }
    const float rmax = red[0];
    __syncthreads();

    float sum = 0.0f;
#pragma unroll
    for (int k = 0; k < 8; k++) {
        vals[k] = expf(vals[k] - rmax);
        sum += vals[k];
    }
    red[t] = sum; __syncthreads();
    for (int s = 128; s > 0; s >>= 1) {
        if (t < s) red[t] += red[t + s];
        __syncthreads();
    }
    const float inv = 1.0f / red[0];
#pragma unroll
    for (int k = 0; k < 8; k++)
        p[t + k * 256] = vals[k] * inv;
}

// ---------------------------------------------------------------------------
// Fused LayerNorm + ReLU, in place. blockDim.x == width (128 or 256).
// ---------------------------------------------------------------------------
__global__ void ln_relu_kernel(float* __restrict__ X,
                               const float* __restrict__ g,
                               const float* __restrict__ beta,
                               int width)
{
    const int row = blockIdx.x;
    const int t = threadIdx.x;
    float v = X[(long long)row * width + t];

    __shared__ float red[256];
    red[t] = v; __syncthreads();
    for (int s = blockDim.x >> 1; s > 0; s >>= 1) {
        if (t < s) red[t] += red[t + s];
        __syncthreads();
    }
    const float mu = red[0] / width;
    __syncthreads();

    const float d = v - mu;
    red[t] = d * d; __syncthreads();
    for (int s = blockDim.x >> 1; s > 0; s >>= 1) {
        if (t < s) red[t] += red[t + s];
        __syncthreads();
    }
    const float var = red[0] / width;

    float y = d * rsqrtf(var + 1e-5f) * g[t] + beta[t];
    X[(long long)row * width + t] = fmaxf(y, 0.0f);
}

// ---------------------------------------------------------------------------
// Final head: base = h2 . w3 + b3 ; weight = clip(base*(1+imp), .1, 5); mask.
// mask is int32. blockDim = 128, blockIdx.x = row.
// ---------------------------------------------------------------------------
__global__ void final_kernel(const float* __restrict__ H2,
                             const float* __restrict__ w3,
                             const float* __restrict__ b3,
                             const int* __restrict__ tok,
                             const int* __restrict__ mask,
                             const float* __restrict__ table,
                             float* __restrict__ out)
{
    const int row = blockIdx.x;
    const int t = threadIdx.x;
    float v = H2[(long long)row * 128 + t] * w3[t];
    __shared__ float red[128];
    red[t] = v; __syncthreads();
    for (int s = 64; s > 0; s >>= 1) {
        if (t < s) red[t] += red[t + s];
        __syncthreads();
    }
    if (t == 0) {
        float base = red[0] + b3[0];
        float imp  = table[tok[row]];
        float w = base * (1.0f + imp);
        w = fminf(fmaxf(w, 0.1f), 5.0f);
        out[row] = (mask[row] != 0) ? w : 0.0f;
    }
}

// ---------------------------------------------------------------------------
// Launch
// ---------------------------------------------------------------------------
extern "C" void kernel_launch(void* const* d_in, const int* in_sizes, int n_in,
                              void* d_out, int out_size)
{
    const float* hidden  = (const float*)d_in[0];
    const int*   tok     = (const int*)  d_in[1];
    const int*   mask    = (const int*)  d_in[2];   // bool -> int32
    const float* pos     = (const float*)d_in[3];
    const float* in_w    = (const float*)d_in[4];   // [3072,1024]
    const float* in_b    = (const float*)d_in[5];
    const float* out_w   = (const float*)d_in[6];   // [1024,1024]
    const float* out_b   = (const float*)d_in[7];
    const float* w1      = (const float*)d_in[8];   // [256,2048]
    const float* b1      = (const float*)d_in[9];
    const float* g1      = (const float*)d_in[10];
    const float* be1     = (const float*)d_in[11];
    const float* w2      = (const float*)d_in[12];  // [128,256]
    const float* b2      = (const float*)d_in[13];
    const float* g2      = (const float*)d_in[14];
    const float* be2     = (const float*)d_in[15];
    const float* w3      = (const float*)d_in[16];  // [1,128]
    const float* b3      = (const float*)d_in[17];
    const float* table   = (const float*)d_in[18];  // [32000]
    float* out = (float*)d_out;

    float *x, *qkv, *scr, *ctx, *att, *h1, *h2;
    { void* p;
      cudaGetSymbolAddress(&p, g_x);   x   = (float*)p;
      cudaGetSymbolAddress(&p, g_qkv); qkv = (float*)p;
      cudaGetSymbolAddress(&p, g_scr); scr = (float*)p;
      cudaGetSymbolAddress(&p, g_ctx); ctx = (float*)p;
      cudaGetSymbolAddress(&p, g_att); att = (float*)p;
      cudaGetSymbolAddress(&p, g_h1);  h1  = (float*)p;
      cudaGetSymbolAddress(&p, g_h2);  h2  = (float*)p;
    }

    const long long SH  = (long long)SS * 3 * HH;   // qkv batch-row stride
    const long long SSQ = (long long)SS * SS;       // one score matrix

    // 1) x = hidden + pos
    add_pos_kernel<<<(ROWS * HH / 4) / 256, 256>>>(hidden, pos, x);

    // 2) qkv = x @ in_w^T + in_b      [8192,3072]
    sgemm_kernel<true><<<dim3(3 * HH / 128, ROWS / 128, 1), 256>>>(
        x, in_w, qkv, ROWS, 3 * HH, HH, HH, HH, 3 * HH,
        0, 0, 0, 0, 0, 0, 1, in_b, 1.0f, 0);

    // 3) scores = Q K^T / sqrt(128)   batched over 32 (b,h)
    sgemm_kernel<true><<<dim3(SS / 128, SS / 128, BB * NHEADS), 256>>>(
        qkv /*Q*/, qkv + HH /*K*/, scr,
        SS, SS, HD, 3 * HH, 3 * HH, SS,
        SH, HD,            // A offsets: per-b, per-h
        SH, HD,            // B offsets
        (long long)NHEADS * SSQ, SSQ,  // C offsets
        NHEADS, nullptr, 0.08838834764831843f, 0);

    // 4) softmax with key mask
    softmax_kernel<<<BB * NHEADS * SS, 256>>>(scr, mask);

    // 5) ctx = P @ V                  batched, NN
    sgemm_kernel<false><<<dim3(1, SS / 128, BB * NHEADS), 256>>>(
        scr, qkv + 2 * HH /*V*/, ctx,
        SS, HD, SS, SS, 3 * HH, HH,
        (long long)NHEADS * SSQ, SSQ,
        SH, HD,
        (long long)SS * HH, HD,
        NHEADS, nullptr, 1.0f, 0);

    // 6) attended = ctx @ out_w^T + out_b
    sgemm_kernel<true><<<dim3(HH / 128, ROWS / 128, 1), 256>>>(
        ctx, out_w, att, ROWS, HH, HH, HH, HH, HH,
        0, 0, 0, 0, 0, 0, 1, out_b, 1.0f, 0);

    // 7) h1 = x @ w1[:, :1024]^T + b1
    sgemm_kernel<true><<<dim3(METAD / 128, ROWS / 128, 1), 256>>>(
        x, w1, h1, ROWS, METAD, HH, HH, 2 * HH, METAD,
        0, 0, 0, 0, 0, 0, 1, b1, 1.0f, 0);

    // 8) h1 += attended @ w1[:, 1024:]^T
    sgemm_kernel<true><<<dim3(METAD / 128, ROWS / 128, 1), 256>>>(
        att, w1 + HH, h1, ROWS, METAD, HH, HH, 2 * HH, METAD,
        0, 0, 0, 0, 0, 0, 1, nullptr, 1.0f, 1);

    // 9) LN + ReLU (width 256)
    ln_relu_kernel<<<ROWS, METAD>>>(h1, g1, be1, METAD);

    // 10) h2 = h1 @ w2^T + b2
    sgemm_kernel<true><<<dim3(1, ROWS / 128, 1), 256>>>(
        h1, w2, h2, ROWS, METAD / 2, METAD, METAD, METAD, METAD / 2,
        0, 0, 0, 0, 0, 0, 1, b2, 1.0f, 0);

    // 11) LN + ReLU (width 128)
    ln_relu_kernel<<<ROWS, METAD / 2>>>(h2, g2, be2, METAD / 2);

    // 12) final head + importance + clamp + mask
    final_kernel<<<ROWS, 128>>>(h2, w3, b3, tok, mask, table, out);
}

// round 4
// speedup vs baseline: 1.1241x; 1.1241x over previous
#include <cuda_runtime.h>
#include <cuda_bf16.h>
#include <math.h>
#include <stdint.h>

// ---------------------------------------------------------------------------
// Problem constants
// ---------------------------------------------------------------------------
#define BB 4
#define SS 2048
#define HH 1024
#define NHEADS 8
#define HD 128
#define ROWS (BB*SS)          // 8192
#define METAD 256

// ---------------------------------------------------------------------------
// Scratch (device globals -- no allocation allowed)
// ---------------------------------------------------------------------------
__device__ float g_x   [(size_t)ROWS * HH];            // 32 MB  x = hidden + pos
__device__ float g_qkv [(size_t)ROWS * 3 * HH];        // 96 MB
__device__ float g_scr [(size_t)BB * NHEADS * SS * SS];// 512 MB attention scores
__device__ float g_ctx [(size_t)ROWS * HH];            // 32 MB
__device__ float g_att [(size_t)ROWS * HH];            // 32 MB
__device__ float g_h1  [(size_t)ROWS * METAD];         // 8 MB
__device__ float g_h2  [(size_t)ROWS * (METAD/2)];     // 4 MB

// ---------------------------------------------------------------------------
// TF32 helpers
// ---------------------------------------------------------------------------
__device__ __forceinline__ uint32_t f2tf(float f) {
    uint32_t u;
    asm("cvt.rna.tf32.f32 %0, %1;" : "=r"(u) : "f"(f));
    return u;
}
__device__ __forceinline__ void mma8(float c[4], const uint32_t a[4], const uint32_t b[2]) {
    asm volatile(
        "mma.sync.aligned.m16n8k8.row.col.f32.tf32.tf32.f32 "
        "{%0,%1,%2,%3}, {%4,%5,%6,%7}, {%8,%9}, {%0,%1,%2,%3};"
        : "+f"(c[0]), "+f"(c[1]), "+f"(c[2]), "+f"(c[3])
        : "r"(a[0]), "r"(a[1]), "r"(a[2]), "r"(a[3]),
          "r"(b[0]), "r"(b[1]));
}

// swizzled [m][k] layout, 16 words per row; kv group xor'd by (m>>1)&3
__device__ __forceinline__ int swz(int m, int k) {
    int kv = k >> 2, j = k & 3;
    return m * 16 + (((kv ^ ((m >> 1) & 3))) << 2) + j;
}

// ---------------------------------------------------------------------------
// TF32x3 compensated tensor-core GEMM:  C = alpha * A * op(B) (+ bias) (+ C)
//   fp32 inputs split into tf32 hi + lo; D = Ahi*Bhi + Ahi*Blo + Alo*Bhi.
//   A : [M,K] row-major fp32.  BT=true: B is [N,K]; BT=false: B is [K,N].
//   Block tile 128x128, K-tile 16, 256 threads (8 warps of 64x32).
//   M,N multiples of 128; K multiple of 16.
// ---------------------------------------------------------------------------
template<bool BT>
__global__ __launch_bounds__(256)
void tmma_kernel(const float* __restrict__ A,
                 const float* __restrict__ B,
                 float* __restrict__ C,
                 int M, int N, int K,
                 int lda, int ldb, int ldc,
                 long long aOuter, long long aInner,
                 long long bOuter, long long bInner,
                 long long cOuter, long long cInner,
                 int innerCount,
                 const float* __restrict__ bias,
                 float alpha, int accumulate)
{
    const int z  = blockIdx.z;
    const int zo = z / innerCount;
    const int zi = z - zo * innerCount;
    A += zo * aOuter + zi * aInner;
    B += zo * bOuter + zi * bInner;
    C += zo * cOuter + zi * cInner;

    __shared__ __align__(16) uint32_t AsH[128 * 16];   // swizzled [m][k] hi
    __shared__ __align__(16) uint32_t AsL[128 * 16];   // lo
    __shared__ __align__(16) uint32_t BsH[16 * 136];   // BT: swizzled [n][k] (2048 used)
    __shared__ __align__(16) uint32_t BsL[16 * 136];   // NN: [k][n] pad 136

    const int t    = threadIdx.x;
    const int lane = t & 31;
    const int warp = t >> 5;
    const int gid  = lane >> 2;     // 0..7
    const int tig  = lane & 3;      // 0..3
    const int m_off = (warp >> 2) * 64;   // 0 / 64
    const int n_off = (warp & 3) * 32;    // 0..96
    const int brow = blockIdx.y * 128;
    const int bcol = blockIdx.x * 128;

    float acc[4][4][4];
#pragma unroll
    for (int mi = 0; mi < 4; mi++)
#pragma unroll
        for (int ni = 0; ni < 4; ni++)
#pragma unroll
            for (int r = 0; r < 4; r++) acc[mi][ni][r] = 0.0f;

    // per-thread load coordinates
    const int aRow0 = t >> 2;          // 0..63   (i adds 64)
    const int aKv   = t & 3;
    const int nKrow = t >> 5;          // 0..7    (i adds 8)  [NN B]
    const int nC4   = t & 31;

    float4 curA[2], curB[2], nxtA[2], nxtB[2];

    auto ldg_tiles = [&](int kt, float4* bufA, float4* bufB) {
#pragma unroll
        for (int i = 0; i < 2; i++) {
            int row = aRow0 + i * 64;
            bufA[i] = *reinterpret_cast<const float4*>(
                A + (long long)(brow + row) * lda + kt + aKv * 4);
        }
        if (BT) {
#pragma unroll
            for (int i = 0; i < 2; i++) {
                int row = aRow0 + i * 64;
                bufB[i] = *reinterpret_cast<const float4*>(
                    B + (long long)(bcol + row) * ldb + kt + aKv * 4);
            }
        } else {
#pragma unroll
            for (int i = 0; i < 2; i++) {
                int krow = nKrow + i * 8;
                bufB[i] = *reinterpret_cast<const float4*>(
                    B + (long long)(kt + krow) * ldb + bcol + nC4 * 4);
            }
        }
    };

    auto split4 = [&](float4 v, uint4& hi, uint4& lo) {
        hi.x = f2tf(v.x); lo.x = f2tf(v.x - __uint_as_float(hi.x));
        hi.y = f2tf(v.y); lo.y = f2tf(v.y - __uint_as_float(hi.y));
        hi.z = f2tf(v.z); lo.z = f2tf(v.z - __uint_as_float(hi.z));
        hi.w = f2tf(v.w); lo.w = f2tf(v.w - __uint_as_float(hi.w));
    };

    auto sts_tiles = [&](const float4* bufA, const float4* bufB) {
#pragma unroll
        for (int i = 0; i < 2; i++) {
            int row = aRow0 + i * 64;
            int base = row * 16 + ((aKv ^ ((row >> 1) & 3)) << 2);
            uint4 hi, lo; split4(bufA[i], hi, lo);
            *reinterpret_cast<uint4*>(&AsH[base]) = hi;
            *reinterpret_cast<uint4*>(&AsL[base]) = lo;
        }
        if (BT) {
#pragma unroll
            for (int i = 0; i < 2; i++) {
                int row = aRow0 + i * 64;
                int base = row * 16 + ((aKv ^ ((row >> 1) & 3)) << 2);
                uint4 hi, lo; split4(bufB[i], hi, lo);
                *reinterpret_cast<uint4*>(&BsH[base]) = hi;
                *reinterpret_cast<uint4*>(&BsL[base]) = lo;
            }
        } else {
#pragma unroll
            for (int i = 0; i < 2; i++) {
                int krow = nKrow + i * 8;
                uint4 hi, lo; split4(bufB[i], hi, lo);
                *reinterpret_cast<uint4*>(&BsH[krow * 136 + nC4 * 4]) = hi;
                *reinterpret_cast<uint4*>(&BsL[krow * 136 + nC4 * 4]) = lo;
            }
        }
    };

    ldg_tiles(0, curA, curB);
    sts_tiles(curA, curB);
    __syncthreads();

    for (int kt = 0; kt < K; kt += 16) {
        const bool more = (kt + 16) < K;
        if (more) ldg_tiles(kt + 16, nxtA, nxtB);

#pragma unroll
        for (int ks = 0; ks < 2; ks++) {
            const int k0 = ks * 8 + tig;      // a0/b0 column
            const int k1 = k0 + 4;            // a2/b1 column
            uint32_t afH[4][4], afL[4][4];
#pragma unroll
            for (int mi = 0; mi < 4; mi++) {
                int m0 = m_off + mi * 16 + gid;
                int i00 = swz(m0,     k0), i10 = swz(m0 + 8, k0);
                int i01 = swz(m0,     k1), i11 = swz(m0 + 8, k1);
                afH[mi][0] = AsH[i00]; afH[mi][1] = AsH[i10];
                afH[mi][2] = AsH[i01]; afH[mi][3] = AsH[i11];
                afL[mi][0] = AsL[i00]; afL[mi][1] = AsL[i10];
                afL[mi][2] = AsL[i01]; afL[mi][3] = AsL[i11];
            }
            uint32_t bfH[4][2], bfL[4][2];
#pragma unroll
            for (int ni = 0; ni < 4; ni++) {
                int n0 = n_off + ni * 8 + gid;
                int j0, j1;
                if (BT) { j0 = swz(n0, k0); j1 = swz(n0, k1); }
                else    { j0 = k0 * 136 + n0; j1 = k1 * 136 + n0; }
                bfH[ni][0] = BsH[j0]; bfH[ni][1] = BsH[j1];
                bfL[ni][0] = BsL[j0]; bfL[ni][1] = BsL[j1];
            }
#pragma unroll
            for (int mi = 0; mi < 4; mi++)
#pragma unroll
                for (int ni = 0; ni < 4; ni++) {
                    mma8(acc[mi][ni], afH[mi], bfH[ni]);
                    mma8(acc[mi][ni], afH[mi], bfL[ni]);
                    mma8(acc[mi][ni], afL[mi], bfH[ni]);
                }
        }
        __syncthreads();
        if (more) {
            sts_tiles(nxtA, nxtB);
            __syncthreads();
        }
    }

    // ---- epilogue: c0=(gid,2tig) c1=(gid,2tig+1) c2,c3 = rows +8 ----
#pragma unroll
    for (int mi = 0; mi < 4; mi++) {
#pragma unroll
        for (int ni = 0; ni < 4; ni++) {
            int m = brow + m_off + mi * 16 + gid;
            int n = bcol + n_off + ni * 8 + 2 * tig;
            float b0 = 0.f, b1 = 0.f;
            if (bias) { b0 = bias[n]; b1 = bias[n + 1]; }
#pragma unroll
            for (int half = 0; half < 2; half++) {
                long long r = m + half * 8;
                float* cp = C + r * (long long)ldc + n;
                float2 v;
                v.x = acc[mi][ni][half * 2 + 0] * alpha + b0;
                v.y = acc[mi][ni][half * 2 + 1] * alpha + b1;
                if (accumulate) {
                    float2 o = *reinterpret_cast<const float2*>(cp);
                    v.x += o.x; v.y += o.y;
                }
                *reinterpret_cast<float2*>(cp) = v;
            }
        }
    }
}

// ---------------------------------------------------------------------------
// x = hidden + pos (broadcast over batch), float4
// ---------------------------------------------------------------------------
__global__ void add_pos_kernel(const float* __restrict__ h,
                               const float* __restrict__ p,
                               float* __restrict__ x)
{
    long long i = (long long)blockIdx.x * blockDim.x + threadIdx.x; // float4 idx
    const long long P4 = (long long)SS * HH / 4;
    float4 hv = reinterpret_cast<const float4*>(h)[i];
    float4 pv = reinterpret_cast<const float4*>(p)[i % P4];
    hv.x += pv.x; hv.y += pv.y; hv.z += pv.z; hv.w += pv.w;
    reinterpret_cast<float4*>(x)[i] = hv;
}

// ---------------------------------------------------------------------------
// Row softmax over 2048 with key-mask (-1e9 where mask==0). mask int32.
// ---------------------------------------------------------------------------
__global__ __launch_bounds__(256)
void softmax_kernel(float* __restrict__ S, const int* __restrict__ mask)
{
    const long long row = blockIdx.x;
    const int b = (int)(row >> 14);            // row / (NHEADS*SS)
    float* p = S + row * (long long)SS;
    const int* mrow = mask + (long long)b * SS;
    const int t = threadIdx.x;

    float vals[8];
    float m = -1e30f;
#pragma unroll
    for (int k = 0; k < 8; k++) {
        int j = t + k * 256;
        float v = p[j];
        v = (mrow[j] != 0) ? v : -1e9f;
        vals[k] = v;
        m = fmaxf(m, v);
    }
    __shared__ float red[256];
    red[t] = m; __syncthreads();
    for (int s = 128; s > 0; s >>= 1) {
        if (t < s) red[t] = fmaxf(red[t], red[t + s]);
        __syncthreads();
    }
    const float rmax = red[0];
    __syncthreads();

    float sum = 0.0f;
#pragma unroll
    for (int k = 0; k < 8; k++) {
        vals[k] = expf(vals[k] - rmax);
        sum += vals[k];
    }
    red[t] = sum; __syncthreads();
    for (int s = 128; s > 0; s >>= 1) {
        if (t < s) red[t] += red[t + s];
        __syncthreads();
    }
    const float inv = 1.0f / red[0];
#pragma unroll
    for (int k = 0; k < 8; k++)
        p[t + k * 256] = vals[k] * inv;
}

// ---------------------------------------------------------------------------
// Fused LayerNorm + ReLU, in place. blockDim.x == width (128 or 256).
// ---------------------------------------------------------------------------
__global__ void ln_relu_kernel(float* __restrict__ X,
                               const float* __restrict__ g,
                               const float* __restrict__ beta,
                               int width)
{
    const int row = blockIdx.x;
    const int t = threadIdx.x;
    float v = X[(long long)row * width + t];

    __shared__ float red[256];
    red[t] = v; __syncthreads();
    for (int s = blockDim.x >> 1; s > 0; s >>= 1) {
        if (t < s) red[t] += red[t + s];
        __syncthreads();
    }
    const float mu = red[0] / width;
    __syncthreads();

    const float d = v - mu;
    red[t] = d * d; __syncthreads();
    for (int s = blockDim.x >> 1; s > 0; s >>= 1) {
        if (t < s) red[t] += red[t + s];
        __syncthreads();
    }
    const float var = red[0] / width;

    float y = d * rsqrtf(var + 1e-5f) * g[t] + beta[t];
    X[(long long)row * width + t] = fmaxf(y, 0.0f);
}

// ---------------------------------------------------------------------------
// Final head: base = h2 . w3 + b3 ; weight = clip(base*(1+imp), .1, 5); mask.
// ---------------------------------------------------------------------------
__global__ void final_kernel(const float* __restrict__ H2,
                             const float* __restrict__ w3,
                             const float* __restrict__ b3,
                             const int* __restrict__ tok,
                             const int* __restrict__ mask,
                             const float* __restrict__ table,
                             float* __restrict__ out)
{
    const int row = blockIdx.x;
    const int t = threadIdx.x;
    float v = H2[(long long)row * 128 + t] * w3[t];
    __shared__ float red[128];
    red[t] = v; __syncthreads();
    for (int s = 64; s > 0; s >>= 1) {
        if (t < s) red[t] += red[t + s];
        __syncthreads();
    }
    if (t == 0) {
        float base = red[0] + b3[0];
        float imp  = table[tok[row]];
        float w = base * (1.0f + imp);
        w = fminf(fmaxf(w, 0.1f), 5.0f);
        out[row] = (mask[row] != 0) ? w : 0.0f;
    }
}

// ---------------------------------------------------------------------------
// Launch
// ---------------------------------------------------------------------------
extern "C" void kernel_launch(void* const* d_in, const int* in_sizes, int n_in,
                              void* d_out, int out_size)
{
    const float* hidden  = (const float*)d_in[0];
    const int*   tok     = (const int*)  d_in[1];
    const int*   mask    = (const int*)  d_in[2];   // bool -> int32
    const float* pos     = (const float*)d_in[3];
    const float* in_w    = (const float*)d_in[4];   // [3072,1024]
    const float* in_b    = (const float*)d_in[5];
    const float* out_w   = (const float*)d_in[6];   // [1024,1024]
    const float* out_b   = (const float*)d_in[7];
    const float* w1      = (const float*)d_in[8];   // [256,2048]
    const float* b1      = (const float*)d_in[9];
    const float* g1      = (const float*)d_in[10];
    const float* be1     = (const float*)d_in[11];
    const float* w2      = (const float*)d_in[12];  // [128,256]
    const float* b2      = (const float*)d_in[13];
    const float* g2      = (const float*)d_in[14];
    const float* be2     = (const float*)d_in[15];
    const float* w3      = (const float*)d_in[16];  // [1,128]
    const float* b3      = (const float*)d_in[17];
    const float* table   = (const float*)d_in[18];  // [32000]
    float* out = (float*)d_out;

    float *x, *qkv, *scr, *ctx, *att, *h1, *h2;
    { void* p;
      cudaGetSymbolAddress(&p, g_x);   x   = (float*)p;
      cudaGetSymbolAddress(&p, g_qkv); qkv = (float*)p;
      cudaGetSymbolAddress(&p, g_scr); scr = (float*)p;
      cudaGetSymbolAddress(&p, g_ctx); ctx = (float*)p;
      cudaGetSymbolAddress(&p, g_att); att = (float*)p;
      cudaGetSymbolAddress(&p, g_h1);  h1  = (float*)p;
      cudaGetSymbolAddress(&p, g_h2);  h2  = (float*)p;
    }

    const long long SH  = (long long)SS * 3 * HH;   // qkv batch-row stride
    const long long SSQ = (long long)SS * SS;       // one score matrix

    // 1) x = hidden + pos
    add_pos_kernel<<<(ROWS * HH / 4) / 256, 256>>>(hidden, pos, x);

    // 2) qkv = x @ in_w^T + in_b      [8192,3072]
    tmma_kernel<true><<<dim3(3 * HH / 128, ROWS / 128, 1), 256>>>(
        x, in_w, qkv, ROWS, 3 * HH, HH, HH, HH, 3 * HH,
        0, 0, 0, 0, 0, 0, 1, in_b, 1.0f, 0);

    // 3) scores = Q K^T / sqrt(128)   batched over 32 (b,h)
    tmma_kernel<true><<<dim3(SS / 128, SS / 128, BB * NHEADS), 256>>>(
        qkv /*Q*/, qkv + HH /*K*/, scr,
        SS, SS, HD, 3 * HH, 3 * HH, SS,
        SH, HD,            // A offsets: per-b, per-h
        SH, HD,            // B offsets
        (long long)NHEADS * SSQ, SSQ,  // C offsets
        NHEADS, nullptr, 0.08838834764831843f, 0);

    // 4) softmax with key mask
    softmax_kernel<<<BB * NHEADS * SS, 256>>>(scr, mask);

    // 5) ctx = P @ V                  batched, NN
    tmma_kernel<false><<<dim3(1, SS / 128, BB * NHEADS), 256>>>(
        scr, qkv + 2 * HH /*V*/, ctx,
        SS, HD, SS, SS, 3 * HH, HH,
        (long long)NHEADS * SSQ, SSQ,
        SH, HD,
        (long long)SS * HH, HD,
        NHEADS, nullptr, 1.0f, 0);

    // 6) attended = ctx @ out_w^T + out_b
    tmma_kernel<true><<<dim3(HH / 128, ROWS / 128, 1), 256>>>(
        ctx, out_w, att, ROWS, HH, HH, HH, HH, HH,
        0, 0, 0, 0, 0, 0, 1, out_b, 1.0f, 0);

    // 7) h1 = x @ w1[:, :1024]^T + b1
    tmma_kernel<true><<<dim3(METAD / 128, ROWS / 128, 1), 256>>>(
        x, w1, h1, ROWS, METAD, HH, HH, 2 * HH, METAD,
        0, 0, 0, 0, 0, 0, 1, b1, 1.0f, 0);

    // 8) h1 += attended @ w1[:, 1024:]^T
    tmma_kernel<true><<<dim3(METAD / 128, ROWS / 128, 1), 256>>>(
        att, w1 + HH, h1, ROWS, METAD, HH, HH, 2 * HH, METAD,
        0, 0, 0, 0, 0, 0, 1, nullptr, 1.0f, 1);

    // 9) LN + ReLU (width 256)
    ln_relu_kernel<<<ROWS, METAD>>>(h1, g1, be1, METAD);

    // 10) h2 = h1 @ w2^T + b2
    tmma_kernel<true><<<dim3(1, ROWS / 128, 1), 256>>>(
        h1, w2, h2, ROWS, METAD / 2, METAD, METAD, METAD, METAD / 2,
        0, 0, 0, 0, 0, 0, 1, b2, 1.0f, 0);

    // 11) LN + ReLU (width 128)
    ln_relu_kernel<<<ROWS, METAD / 2>>>(h2, g2, be2, METAD / 2);

    // 12) final head + importance + clamp + mask
    final_kernel<<<ROWS, 128>>>(h2, w3, b3, tok, mask, table, out);
}

// round 5
// speedup vs baseline: 1.9032x; 1.6932x over previous
#include <cuda_runtime.h>
#include <cuda_bf16.h>
#include <math.h>
#include <stdint.h>

// ---------------------------------------------------------------------------
// Problem constants
// ---------------------------------------------------------------------------
#define BB 4
#define SS 2048
#define HH 1024
#define NHEADS 8
#define HD 128
#define ROWS (BB*SS)          // 8192
#define METAD 256

// ---------------------------------------------------------------------------
// Scratch (device globals -- no allocation allowed)
// ---------------------------------------------------------------------------
__device__ float g_x   [(size_t)ROWS * HH];            // 32 MB  x = hidden + pos
__device__ float g_qkv [(size_t)ROWS * 3 * HH];        // 96 MB
__device__ float g_scr [(size_t)BB * NHEADS * SS * SS];// 512 MB attention scores
__device__ float g_ctx [(size_t)ROWS * HH];            // 32 MB
__device__ float g_att [(size_t)ROWS * HH];            // 32 MB
__device__ float g_h1  [(size_t)ROWS * METAD];         // 8 MB
__device__ float g_h2  [(size_t)ROWS * (METAD/2)];     // 4 MB

// ---------------------------------------------------------------------------
// bf16 helpers
// ---------------------------------------------------------------------------
__device__ __forceinline__ uint32_t pbf2(float e, float o) {
    __nv_bfloat162 p;
    p.x = __float2bfloat16_rn(e);
    p.y = __float2bfloat16_rn(o);
    return *reinterpret_cast<uint32_t*>(&p);
}
// split pair (e,o) into packed hi word and packed lo word
__device__ __forceinline__ void sp2(float e, float o, uint32_t& hi, uint32_t& lo) {
    __nv_bfloat16 he = __float2bfloat16_rn(e);
    __nv_bfloat16 ho = __float2bfloat16_rn(o);
    float le = e - __bfloat162float(he);
    float lof = o - __bfloat162float(ho);
    __nv_bfloat162 ph; ph.x = he; ph.y = ho;
    hi = *reinterpret_cast<uint32_t*>(&ph);
    lo = pbf2(le, lof);
}
__device__ __forceinline__ void mma16(float c[4], const uint32_t a[4], const uint32_t b[2]) {
    asm volatile(
        "mma.sync.aligned.m16n8k16.row.col.f32.bf16.bf16.f32 "
        "{%0,%1,%2,%3}, {%4,%5,%6,%7}, {%8,%9}, {%0,%1,%2,%3};"
        : "+f"(c[0]), "+f"(c[1]), "+f"(c[2]), "+f"(c[3])
        : "r"(a[0]), "r"(a[1]), "r"(a[2]), "r"(a[3]),
          "r"(b[0]), "r"(b[1]));
}

// swizzled [m][kw] layout, 16 packed words per row; word-group xor'd by (m>>1)&3
__device__ __forceinline__ int swz(int m, int kw) {
    int g = kw >> 2, j = kw & 3;
    return m * 16 + ((g ^ ((m >> 1) & 3)) << 2) + j;
}

// ---------------------------------------------------------------------------
// bf16x3 compensated tensor-core GEMM:  C = alpha * A * op(B) (+ bias) (+ C)
//   fp32 inputs split into bf16 hi + lo; D = Ahi*Bhi + Ahi*Blo + Alo*Bhi.
//   A : [M,K] row-major fp32.  BT=true: B is [N,K]; BT=false: B is [K,N].
//   Block tile 128x128, K-tile 32, 256 threads (8 warps of 64x32),
//   mma.sync m16n8k16 bf16, fp32 accumulate.
//   M,N multiples of 128; K multiple of 32.
// ---------------------------------------------------------------------------
template<bool BT>
__global__ __launch_bounds__(256)
void bmma_kernel(const float* __restrict__ A,
                 const float* __restrict__ B,
                 float* __restrict__ C,
                 int M, int N, int K,
                 int lda, int ldb, int ldc,
                 long long aOuter, long long aInner,
                 long long bOuter, long long bInner,
                 long long cOuter, long long cInner,
                 int innerCount,
                 const float* __restrict__ bias,
                 float alpha, int accumulate)
{
    const int z  = blockIdx.z;
    const int zo = z / innerCount;
    const int zi = z - zo * innerCount;
    A += zo * aOuter + zi * aInner;
    B += zo * bOuter + zi * bInner;
    C += zo * cOuter + zi * cInner;

    // A: 128 rows x 16 packed words (32 k), swizzled.
    // B BT: same geometry as A (n rows).  B NN: 16 kpair rows x 136-pitch words.
    __shared__ __align__(16) uint32_t AsH[128 * 16];
    __shared__ __align__(16) uint32_t AsL[128 * 16];
    __shared__ __align__(16) uint32_t BsH[16 * 136];
    __shared__ __align__(16) uint32_t BsL[16 * 136];

    const int t    = threadIdx.x;
    const int lane = t & 31;
    const int warp = t >> 5;
    const int gid  = lane >> 2;     // 0..7
    const int tig  = lane & 3;      // 0..3
    const int m_off = (warp >> 2) * 64;   // 0 / 64
    const int n_off = (warp & 3) * 32;    // 0..96
    const int brow = blockIdx.y * 128;
    const int bcol = blockIdx.x * 128;

    float acc[4][4][4];
#pragma unroll
    for (int mi = 0; mi < 4; mi++)
#pragma unroll
        for (int ni = 0; ni < 4; ni++)
#pragma unroll
            for (int r = 0; r < 4; r++) acc[mi][ni][r] = 0.0f;

    float4 curA[2][2], curB[2][2], nxtA[2][2], nxtB[2][2];

    // ---- global loads: one k-tile = 32 floats deep ----
    auto ldg_tiles = [&](int kt, float4 bufA[2][2], float4 bufB[2][2]) {
#pragma unroll
        for (int i = 0; i < 2; i++) {
            int idx = t + i * 256;
            int row = idx >> 2;            // 0..127
            int quad = idx & 3;            // packed-word quad -> floats quad*8..+7
            const float* p = A + (long long)(brow + row) * lda + kt + quad * 8;
            bufA[i][0] = *reinterpret_cast<const float4*>(p);
            bufA[i][1] = *reinterpret_cast<const float4*>(p + 4);
        }
        if (BT) {
#pragma unroll
            for (int i = 0; i < 2; i++) {
                int idx = t + i * 256;
                int row = idx >> 2;
                int quad = idx & 3;
                const float* p = B + (long long)(bcol + row) * ldb + kt + quad * 8;
                bufB[i][0] = *reinterpret_cast<const float4*>(p);
                bufB[i][1] = *reinterpret_cast<const float4*>(p + 4);
            }
        } else {
#pragma unroll
            for (int i = 0; i < 2; i++) {
                int idx = t + i * 256;
                int kp = idx >> 5;             // 0..15 (k pair row)
                int q  = idx & 31;             // n quad
                const float* p0 = B + (long long)(kt + 2 * kp) * ldb + bcol + q * 4;
                bufB[i][0] = *reinterpret_cast<const float4*>(p0);        // k even
                bufB[i][1] = *reinterpret_cast<const float4*>(p0 + ldb);  // k odd
            }
        }
    };

    // pack 8 consecutive-k floats (two float4) -> 4 hi words + 4 lo words
    auto pack_k8 = [&](const float4& a, const float4& b, uint4& hi, uint4& lo) {
        sp2(a.x, a.y, hi.x, lo.x);
        sp2(a.z, a.w, hi.y, lo.y);
        sp2(b.x, b.y, hi.z, lo.z);
        sp2(b.z, b.w, hi.w, lo.w);
    };
    // pack across two k rows: word j = (r0[j], r1[j])
    auto pack_kp = [&](const float4& r0, const float4& r1, uint4& hi, uint4& lo) {
        sp2(r0.x, r1.x, hi.x, lo.x);
        sp2(r0.y, r1.y, hi.y, lo.y);
        sp2(r0.z, r1.z, hi.z, lo.z);
        sp2(r0.w, r1.w, hi.w, lo.w);
    };

    auto sts_tiles = [&](const float4 bufA[2][2], const float4 bufB[2][2]) {
#pragma unroll
        for (int i = 0; i < 2; i++) {
            int idx = t + i * 256;
            int row = idx >> 2;
            int quad = idx & 3;
            int base = row * 16 + ((quad ^ ((row >> 1) & 3)) << 2);
            uint4 hi, lo;
            pack_k8(bufA[i][0], bufA[i][1], hi, lo);
            *reinterpret_cast<uint4*>(&AsH[base]) = hi;
            *reinterpret_cast<uint4*>(&AsL[base]) = lo;
        }
        if (BT) {
#pragma unroll
            for (int i = 0; i < 2; i++) {
                int idx = t + i * 256;
                int row = idx >> 2;
                int quad = idx & 3;
                int base = row * 16 + ((quad ^ ((row >> 1) & 3)) << 2);
                uint4 hi, lo;
                pack_k8(bufB[i][0], bufB[i][1], hi, lo);
                *reinterpret_cast<uint4*>(&BsH[base]) = hi;
                *reinterpret_cast<uint4*>(&BsL[base]) = lo;
            }
        } else {
#pragma unroll
            for (int i = 0; i < 2; i++) {
                int idx = t + i * 256;
                int kp = idx >> 5;
                int q  = idx & 31;
                int base = kp * 136 + q * 4;
                uint4 hi, lo;
                pack_kp(bufB[i][0], bufB[i][1], hi, lo);
                *reinterpret_cast<uint4*>(&BsH[base]) = hi;
                *reinterpret_cast<uint4*>(&BsL[base]) = lo;
            }
        }
    };

    ldg_tiles(0, curA, curB);
    sts_tiles(curA, curB);
    __syncthreads();

    for (int kt = 0; kt < K; kt += 32) {
        const bool more = (kt + 32) < K;
        if (more) ldg_tiles(kt + 32, nxtA, nxtB);

#pragma unroll
        for (int ks = 0; ks < 2; ks++) {
            const int k0 = ks * 8 + tig;      // packed-word col for a0/a1 & b0
            const int k1 = k0 + 4;            // a2/a3 & b1
            uint32_t bH[4][2], bL[4][2];
#pragma unroll
            for (int ni = 0; ni < 4; ni++) {
                int n0 = n_off + ni * 8 + gid;
                int j0, j1;
                if (BT) { j0 = swz(n0, k0); j1 = swz(n0, k1); }
                else    { j0 = k0 * 136 + n0; j1 = k1 * 136 + n0; }
                bH[ni][0] = BsH[j0]; bH[ni][1] = BsH[j1];
                bL[ni][0] = BsL[j0]; bL[ni][1] = BsL[j1];
            }
#pragma unroll
            for (int mi = 0; mi < 4; mi++) {
                int m0 = m_off + mi * 16 + gid;
                int i00 = swz(m0,     k0), i10 = swz(m0 + 8, k0);
                int i01 = swz(m0,     k1), i11 = swz(m0 + 8, k1);
                uint32_t aH[4] = {AsH[i00], AsH[i10], AsH[i01], AsH[i11]};
                uint32_t aL[4] = {AsL[i00], AsL[i10], AsL[i01], AsL[i11]};
#pragma unroll
                for (int ni = 0; ni < 4; ni++) {
                    mma16(acc[mi][ni], aH, bH[ni]);
                    mma16(acc[mi][ni], aH, bL[ni]);
                    mma16(acc[mi][ni], aL, bH[ni]);
                }
            }
        }
        __syncthreads();
        if (more) {
            sts_tiles(nxtA, nxtB);
            __syncthreads();
        }
    }

    // ---- epilogue: c0=(gid,2tig) c1=(gid,2tig+1) c2,c3 = rows +8 ----
#pragma unroll
    for (int mi = 0; mi < 4; mi++) {
#pragma unroll
        for (int ni = 0; ni < 4; ni++) {
            int m = brow + m_off + mi * 16 + gid;
            int n = bcol + n_off + ni * 8 + 2 * tig;
            float b0 = 0.f, b1 = 0.f;
            if (bias) { b0 = bias[n]; b1 = bias[n + 1]; }
#pragma unroll
            for (int half = 0; half < 2; half++) {
                long long r = m + half * 8;
                float* cp = C + r * (long long)ldc + n;
                float2 v;
                v.x = acc[mi][ni][half * 2 + 0] * alpha + b0;
                v.y = acc[mi][ni][half * 2 + 1] * alpha + b1;
                if (accumulate) {
                    float2 o = *reinterpret_cast<const float2*>(cp);
                    v.x += o.x; v.y += o.y;
                }
                *reinterpret_cast<float2*>(cp) = v;
            }
        }
    }
}

// ---------------------------------------------------------------------------
// x = hidden + pos (broadcast over batch), float4
// ---------------------------------------------------------------------------
__global__ void add_pos_kernel(const float* __restrict__ h,
                               const float* __restrict__ p,
                               float* __restrict__ x)
{
    long long i = (long long)blockIdx.x * blockDim.x + threadIdx.x; // float4 idx
    const long long P4 = (long long)SS * HH / 4;
    float4 hv = reinterpret_cast<const float4*>(h)[i];
    float4 pv = reinterpret_cast<const float4*>(p)[i % P4];
    hv.x += pv.x; hv.y += pv.y; hv.z += pv.z; hv.w += pv.w;
    reinterpret_cast<float4*>(x)[i] = hv;
}

// ---------------------------------------------------------------------------
// Row softmax over 2048 with key-mask (-1e9 where mask==0). mask int32.
// ---------------------------------------------------------------------------
__global__ __launch_bounds__(256)
void softmax_kernel(float* __restrict__ S, const int* __restrict__ mask)
{
    const long long row = blockIdx.x;
    const int b = (int)(row >> 14);            // row / (NHEADS*SS)
    float* p = S + row * (long long)SS;
    const int* mrow = mask + (long long)b * SS;
    const int t = threadIdx.x;

    float vals[8];
    float m = -1e30f;
#pragma unroll
    for (int k = 0; k < 8; k++) {
        int j = t + k * 256;
        float v = p[j];
        v = (mrow[j] != 0) ? v : -1e9f;
        vals[k] = v;
        m = fmaxf(m, v);
    }
    __shared__ float red[256];
    red[t] = m; __syncthreads();
    for (int s = 128; s > 0; s >>= 1) {
        if (t < s) red[t] = fmaxf(red[t], red[t + s]);
        __syncthreads();
    }
    const float rmax = red[0];
    __syncthreads();

    float sum = 0.0f;
#pragma unroll
    for (int k = 0; k < 8; k++) {
        vals[k] = expf(vals[k] - rmax);
        sum += vals[k];
    }
    red[t] = sum; __syncthreads();
    for (int s = 128; s > 0; s >>= 1) {
        if (t < s) red[t] += red[t + s];
        __syncthreads();
    }
    const float inv = 1.0f / red[0];
#pragma unroll
    for (int k = 0; k < 8; k++)
        p[t + k * 256] = vals[k] * inv;
}

// ---------------------------------------------------------------------------
// Fused LayerNorm + ReLU, in place. blockDim.x == width (128 or 256).
// ---------------------------------------------------------------------------
__global__ void ln_relu_kernel(float* __restrict__ X,
                               const float* __restrict__ g,
                               const float* __restrict__ beta,
                               int width)
{
    const int row = blockIdx.x;
    const int t = threadIdx.x;
    float v = X[(long long)row * width + t];

    __shared__ float red[256];
    red[t] = v; __syncthreads();
    for (int s = blockDim.x >> 1; s > 0; s >>= 1) {
        if (t < s) red[t] += red[t + s];
        __syncthreads();
    }
    const float mu = red[0] / width;
    __syncthreads();

    const float d = v - mu;
    red[t] = d * d; __syncthreads();
    for (int s = blockDim.x >> 1; s > 0; s >>= 1) {
        if (t < s) red[t] += red[t + s];
        __syncthreads();
    }
    const float var = red[0] / width;

    float y = d * rsqrtf(var + 1e-5f) * g[t] + beta[t];
    X[(long long)row * width + t] = fmaxf(y, 0.0f);
}

// ---------------------------------------------------------------------------
// Final head: base = h2 . w3 + b3 ; weight = clip(base*(1+imp), .1, 5); mask.
// ---------------------------------------------------------------------------
__global__ void final_kernel(const float* __restrict__ H2,
                             const float* __restrict__ w3,
                             const float* __restrict__ b3,
                             const int* __restrict__ tok,
                             const int* __restrict__ mask,
                             const float* __restrict__ table,
                             float* __restrict__ out)
{
    const int row = blockIdx.x;
    const int t = threadIdx.x;
    float v = H2[(long long)row * 128 + t] * w3[t];
    __shared__ float red[128];
    red[t] = v; __syncthreads();
    for (int s = 64; s > 0; s >>= 1) {
        if (t < s) red[t] += red[t + s];
        __syncthreads();
    }
    if (t == 0) {
        float base = red[0] + b3[0];
        float imp  = table[tok[row]];
        float w = base * (1.0f + imp);
        w = fminf(fmaxf(w, 0.1f), 5.0f);
        out[row] = (mask[row] != 0) ? w : 0.0f;
    }
}

// ---------------------------------------------------------------------------
// Launch
// ---------------------------------------------------------------------------
extern "C" void kernel_launch(void* const* d_in, const int* in_sizes, int n_in,
                              void* d_out, int out_size)
{
    const float* hidden  = (const float*)d_in[0];
    const int*   tok     = (const int*)  d_in[1];
    const int*   mask    = (const int*)  d_in[2];   // bool -> int32
    const float* pos     = (const float*)d_in[3];
    const float* in_w    = (const float*)d_in[4];   // [3072,1024]
    const float* in_b    = (const float*)d_in[5];
    const float* out_w   = (const float*)d_in[6];   // [1024,1024]
    const float* out_b   = (const float*)d_in[7];
    const float* w1      = (const float*)d_in[8];   // [256,2048]
    const float* b1      = (const float*)d_in[9];
    const float* g1      = (const float*)d_in[10];
    const float* be1     = (const float*)d_in[11];
    const float* w2      = (const float*)d_in[12];  // [128,256]
    const float* b2      = (const float*)d_in[13];
    const float* g2      = (const float*)d_in[14];
    const float* be2     = (const float*)d_in[15];
    const float* w3      = (const float*)d_in[16];  // [1,128]
    const float* b3      = (const float*)d_in[17];
    const float* table   = (const float*)d_in[18];  // [32000]
    float* out = (float*)d_out;

    float *x, *qkv, *scr, *ctx, *att, *h1, *h2;
    { void* p;
      cudaGetSymbolAddress(&p, g_x);   x   = (float*)p;
      cudaGetSymbolAddress(&p, g_qkv); qkv = (float*)p;
      cudaGetSymbolAddress(&p, g_scr); scr = (float*)p;
      cudaGetSymbolAddress(&p, g_ctx); ctx = (float*)p;
      cudaGetSymbolAddress(&p, g_att); att = (float*)p;
      cudaGetSymbolAddress(&p, g_h1);  h1  = (float*)p;
      cudaGetSymbolAddress(&p, g_h2);  h2  = (float*)p;
    }

    const long long SH  = (long long)SS * 3 * HH;   // qkv batch-row stride
    const long long SSQ = (long long)SS * SS;       // one score matrix

    // 1) x = hidden + pos
    add_pos_kernel<<<(ROWS * HH / 4) / 256, 256>>>(hidden, pos, x);

    // 2) qkv = x @ in_w^T + in_b      [8192,3072]
    bmma_kernel<true><<<dim3(3 * HH / 128, ROWS / 128, 1), 256>>>(
        x, in_w, qkv, ROWS, 3 * HH, HH, HH, HH, 3 * HH,
        0, 0, 0, 0, 0, 0, 1, in_b, 1.0f, 0);

    // 3) scores = Q K^T / sqrt(128)   batched over 32 (b,h)
    bmma_kernel<true><<<dim3(SS / 128, SS / 128, BB * NHEADS), 256>>>(
        qkv /*Q*/, qkv + HH /*K*/, scr,
        SS, SS, HD, 3 * HH, 3 * HH, SS,
        SH, HD,            // A offsets: per-b, per-h
        SH, HD,            // B offsets
        (long long)NHEADS * SSQ, SSQ,  // C offsets
        NHEADS, nullptr, 0.08838834764831843f, 0);

    // 4) softmax with key mask
    softmax_kernel<<<BB * NHEADS * SS, 256>>>(scr, mask);

    // 5) ctx = P @ V                  batched, NN
    bmma_kernel<false><<<dim3(1, SS / 128, BB * NHEADS), 256>>>(
        scr, qkv + 2 * HH /*V*/, ctx,
        SS, HD, SS, SS, 3 * HH, HH,
        (long long)NHEADS * SSQ, SSQ,
        SH, HD,
        (long long)SS * HH, HD,
        NHEADS, nullptr, 1.0f, 0);

    // 6) attended = ctx @ out_w^T + out_b
    bmma_kernel<true><<<dim3(HH / 128, ROWS / 128, 1), 256>>>(
        ctx, out_w, att, ROWS, HH, HH, HH, HH, HH,
        0, 0, 0, 0, 0, 0, 1, out_b, 1.0f, 0);

    // 7) h1 = x @ w1[:, :1024]^T + b1
    bmma_kernel<true><<<dim3(METAD / 128, ROWS / 128, 1), 256>>>(
        x, w1, h1, ROWS, METAD, HH, HH, 2 * HH, METAD,
        0, 0, 0, 0, 0, 0, 1, b1, 1.0f, 0);

    // 8) h1 += attended @ w1[:, 1024:]^T
    bmma_kernel<true><<<dim3(METAD / 128, ROWS / 128, 1), 256>>>(
        att, w1 + HH, h1, ROWS, METAD, HH, HH, 2 * HH, METAD,
        0, 0, 0, 0, 0, 0, 1, nullptr, 1.0f, 1);

    // 9) LN + ReLU (width 256)
    ln_relu_kernel<<<ROWS, METAD>>>(h1, g1, be1, METAD);

    // 10) h2 = h1 @ w2^T + b2
    bmma_kernel<true><<<dim3(1, ROWS / 128, 1), 256>>>(
        h1, w2, h2, ROWS, METAD / 2, METAD, METAD, METAD, METAD / 2,
        0, 0, 0, 0, 0, 0, 1, b2, 1.0f, 0);

    // 11) LN + ReLU (width 128)
    ln_relu_kernel<<<ROWS, METAD / 2>>>(h2, g2, be2, METAD / 2);

    // 12) final head + importance + clamp + mask
    final_kernel<<<ROWS, 128>>>(h2, w3, b3, tok, mask, table, out);
}